// round 1
// baseline (speedup 1.0000x reference)
#include <cuda_runtime.h>

#define NFEAT 512
#define HID   128
#define NCLS  64
#define NMAX  50048

// Scratch (device globals -- no allocation allowed in kernel_launch)
__device__ float g_deg [NMAX];
__device__ float g_dinv[NMAX];
__device__ float g_H1  [(size_t)NMAX * HID];
__device__ float g_agg1[(size_t)NMAX * HID];
__device__ float g_H2  [(size_t)NMAX * NCLS];

// ---------------- degree / norm ----------------
__global__ void k_deg_init(int N) {
    int i = blockIdx.x * blockDim.x + threadIdx.x;
    if (i < N) g_deg[i] = 1.0f;   // self loop
}

__global__ void k_deg_acc(const int* __restrict__ ei, int E) {
    int e = blockIdx.x * blockDim.x + threadIdx.x;
    if (e < E) atomicAdd(&g_deg[ei[E + e]], 1.0f);   // dst = ei[1][e]
}

__global__ void k_dinv(int N) {
    int i = blockIdx.x * blockDim.x + threadIdx.x;
    if (i < N) g_dinv[i] = rsqrtf(g_deg[i]);
}

// ---------------- GEMM1: H1 = X @ W1  (N x 512 @ 512 x 128) ----------------
// BM=64 BN=128 BK=32, 256 threads, thread tile 8x4
__global__ __launch_bounds__(256) void k_gemm1(const float* __restrict__ X,
                                               const float* __restrict__ W,
                                               int N) {
    __shared__ float Xs[64][32];
    __shared__ float Ws[32][128];

    int tid = threadIdx.x;
    int ty  = tid >> 5;          // 0..7  (row group)
    int tx  = tid & 31;          // 0..31 (col group)
    int rowBase = blockIdx.x * 64;

    float acc[8][4];
    #pragma unroll
    for (int r = 0; r < 8; r++)
        #pragma unroll
        for (int c = 0; c < 4; c++) acc[r][c] = 0.0f;

    int lr = tid >> 3;            // 0..31
    int lc = (tid & 7) * 4;       // 0..28
    int wr = tid >> 5;            // 0..7
    int wc = (tid & 31) * 4;      // 0..124

    for (int kt = 0; kt < NFEAT; kt += 32) {
        #pragma unroll
        for (int h = 0; h < 2; h++) {
            int r = lr + 32 * h;
            int grow = rowBase + r;
            float4 v = make_float4(0.f, 0.f, 0.f, 0.f);
            if (grow < N)
                v = *(const float4*)(X + (size_t)grow * NFEAT + kt + lc);
            *(float4*)&Xs[r][lc] = v;
        }
        #pragma unroll
        for (int j = 0; j < 4; j++) {
            int r = wr + 8 * j;
            *(float4*)&Ws[r][wc] =
                *(const float4*)(W + (size_t)(kt + r) * HID + wc);
        }
        __syncthreads();

        #pragma unroll
        for (int k = 0; k < 32; k++) {
            float4 b = *(const float4*)&Ws[k][tx * 4];
            #pragma unroll
            for (int r = 0; r < 8; r++) {
                float a = Xs[ty * 8 + r][k];
                acc[r][0] += a * b.x;
                acc[r][1] += a * b.y;
                acc[r][2] += a * b.z;
                acc[r][3] += a * b.w;
            }
        }
        __syncthreads();
    }

    #pragma unroll
    for (int r = 0; r < 8; r++) {
        int grow = rowBase + ty * 8 + r;
        if (grow < N)
            *(float4*)(g_H1 + (size_t)grow * HID + tx * 4) =
                make_float4(acc[r][0], acc[r][1], acc[r][2], acc[r][3]);
    }
}

// ---------------- self-loop init layer 1: agg1 = dinv^2 * H1 + b1 ----------------
__global__ void k_self1(const float* __restrict__ b1, int N) {
    int idx = blockIdx.x * blockDim.x + threadIdx.x;   // over N*32 float4
    if (idx >= N * 32) return;
    int i = idx >> 5;
    int c = idx & 31;
    float s = g_dinv[i]; s = s * s;
    float4 h = ((const float4*)g_H1)[idx];
    float4 b = ((const float4*)b1)[c];
    ((float4*)g_agg1)[idx] =
        make_float4(h.x * s + b.x, h.y * s + b.y, h.z * s + b.z, h.w * s + b.w);
}

// ---------------- edge aggregation layer 1 (warp per edge, 128 feats) ----------------
__global__ __launch_bounds__(256) void k_edge1(const int* __restrict__ ei, int E) {
    int w    = (blockIdx.x * blockDim.x + threadIdx.x) >> 5;
    int lane = threadIdx.x & 31;
    if (w >= E) return;
    int s = ei[w];
    int d = ei[E + w];
    float nrm = g_dinv[s] * g_dinv[d];
    float4 v = ((const float4*)(g_H1 + (size_t)s * HID))[lane];
    float* o = g_agg1 + (size_t)d * HID + lane * 4;
    atomicAdd(o + 0, v.x * nrm);
    atomicAdd(o + 1, v.y * nrm);
    atomicAdd(o + 2, v.z * nrm);
    atomicAdd(o + 3, v.w * nrm);
}

// ---------------- GEMM2: H2 = relu(agg1) @ W2  (N x 128 @ 128 x 64) ----------------
// BM=64 BN=64 BK=32, 256 threads, thread tile 4x4
__global__ __launch_bounds__(256) void k_gemm2(const float* __restrict__ W, int N) {
    __shared__ float Xs[64][32];
    __shared__ float Ws[32][64];

    int tid = threadIdx.x;
    int ty  = tid >> 4;          // 0..15
    int tx  = tid & 15;          // 0..15
    int rowBase = blockIdx.x * 64;

    float acc[4][4];
    #pragma unroll
    for (int r = 0; r < 4; r++)
        #pragma unroll
        for (int c = 0; c < 4; c++) acc[r][c] = 0.0f;

    int lr = tid >> 3;            // 0..31
    int lc = (tid & 7) * 4;
    int wr = tid >> 4;            // 0..15
    int wc = (tid & 15) * 4;

    for (int kt = 0; kt < HID; kt += 32) {
        #pragma unroll
        for (int h = 0; h < 2; h++) {
            int r = lr + 32 * h;
            int grow = rowBase + r;
            float4 v = make_float4(0.f, 0.f, 0.f, 0.f);
            if (grow < N) {
                v = *(const float4*)(g_agg1 + (size_t)grow * HID + kt + lc);
                v.x = fmaxf(v.x, 0.f); v.y = fmaxf(v.y, 0.f);
                v.z = fmaxf(v.z, 0.f); v.w = fmaxf(v.w, 0.f);
            }
            *(float4*)&Xs[r][lc] = v;
        }
        #pragma unroll
        for (int j = 0; j < 2; j++) {
            int r = wr + 16 * j;
            *(float4*)&Ws[r][wc] =
                *(const float4*)(W + (size_t)(kt + r) * NCLS + wc);
        }
        __syncthreads();

        #pragma unroll
        for (int k = 0; k < 32; k++) {
            float4 b = *(const float4*)&Ws[k][tx * 4];
            #pragma unroll
            for (int r = 0; r < 4; r++) {
                float a = Xs[ty * 4 + r][k];
                acc[r][0] += a * b.x;
                acc[r][1] += a * b.y;
                acc[r][2] += a * b.z;
                acc[r][3] += a * b.w;
            }
        }
        __syncthreads();
    }

    #pragma unroll
    for (int r = 0; r < 4; r++) {
        int grow = rowBase + ty * 4 + r;
        if (grow < N)
            *(float4*)(g_H2 + (size_t)grow * NCLS + tx * 4) =
                make_float4(acc[r][0], acc[r][1], acc[r][2], acc[r][3]);
    }
}

// ---------------- self-loop init layer 2: out = dinv^2 * H2 + b2 ----------------
__global__ void k_self2(const float* __restrict__ b2, float* __restrict__ out, int N) {
    int idx = blockIdx.x * blockDim.x + threadIdx.x;   // over N*16 float4
    if (idx >= N * 16) return;
    int i = idx >> 4;
    int c = idx & 15;
    float s = g_dinv[i]; s = s * s;
    float4 h = ((const float4*)g_H2)[idx];
    float4 b = ((const float4*)b2)[c];
    ((float4*)out)[idx] =
        make_float4(h.x * s + b.x, h.y * s + b.y, h.z * s + b.z, h.w * s + b.w);
}

// ---------------- edge aggregation layer 2 (16 threads per edge, 64 feats) ----------------
__global__ __launch_bounds__(256) void k_edge2(const int* __restrict__ ei, int E,
                                               float* __restrict__ out) {
    int t = blockIdx.x * blockDim.x + threadIdx.x;
    int e = t >> 4;
    int c = t & 15;
    if (e >= E) return;
    int s = ei[e];
    int d = ei[E + e];
    float nrm = g_dinv[s] * g_dinv[d];
    float4 v = ((const float4*)(g_H2 + (size_t)s * NCLS))[c];
    float* o = out + (size_t)d * NCLS + c * 4;
    atomicAdd(o + 0, v.x * nrm);
    atomicAdd(o + 1, v.y * nrm);
    atomicAdd(o + 2, v.z * nrm);
    atomicAdd(o + 3, v.w * nrm);
}

extern "C" void kernel_launch(void* const* d_in, const int* in_sizes, int n_in,
                              void* d_out, int out_size) {
    const float* x  = (const float*)d_in[0];
    const int*   ei = (const int*)  d_in[1];
    const float* W1 = (const float*)d_in[2];
    const float* b1 = (const float*)d_in[3];
    const float* W2 = (const float*)d_in[4];
    const float* b2 = (const float*)d_in[5];
    float* out = (float*)d_out;

    int N = in_sizes[0] / NFEAT;   // 50000
    int E = in_sizes[1] / 2;       // 640000

    k_deg_init<<<(N + 255) / 256, 256>>>(N);
    k_deg_acc <<<(E + 255) / 256, 256>>>(ei, E);
    k_dinv    <<<(N + 255) / 256, 256>>>(N);

    k_gemm1<<<(N + 63) / 64, 256>>>(x, W1, N);
    k_self1<<<(N * 32 + 255) / 256, 256>>>(b1, N);
    k_edge1<<<(E + 7) / 8, 256>>>(ei, E);          // 8 warps per block, warp per edge

    k_gemm2<<<(N + 63) / 64, 256>>>(W2, N);
    k_self2<<<(N * 16 + 255) / 256, 256>>>(b2, out, N);
    k_edge2<<<(E * 16 + 255) / 256, 256>>>(ei, E, out);
}

// round 2
// speedup vs baseline: 1.7583x; 1.7583x over previous
#include <cuda_runtime.h>

#define NFEAT 512
#define HID   128
#define NCLS  64
#define NMAX  50048
#define EMAX  640000

// ---------------- device scratch (no allocation allowed) ----------------
__device__ float g_dinv[NMAX];
__device__ int   g_cnt [NMAX];          // per-dst edge count (excl. self loop)
__device__ int   g_excl[NMAX];          // within-block exclusive scan
__device__ int   g_bsum[256];           // per-block sums
__device__ int   g_boff[256];           // scanned block offsets
__device__ int   g_rs  [NMAX + 1];      // CSR row starts
__device__ int   g_cur [NMAX];          // scatter cursors
__device__ int2  g_csr [EMAX];          // (src, norm-as-int) per edge, grouped by dst
__device__ float g_H1  [(size_t)NMAX * HID];
__device__ float g_agg1[(size_t)NMAX * HID];   // relu(conv1) output
__device__ float g_H2  [(size_t)NMAX * NCLS];

// ---------------- degree count ----------------
__global__ void k_cnt_init(int N) {
    int i = blockIdx.x * blockDim.x + threadIdx.x;
    if (i < N) g_cnt[i] = 0;
}

__global__ void k_cnt_acc(const int* __restrict__ ei, int E) {
    int e = blockIdx.x * blockDim.x + threadIdx.x;
    if (e < E) atomicAdd(&g_cnt[ei[E + e]], 1);   // dst = ei[1][e]
}

__global__ void k_dinv(int N) {
    int i = blockIdx.x * blockDim.x + threadIdx.x;
    if (i < N) g_dinv[i] = rsqrtf((float)(g_cnt[i] + 1));  // +1 self loop
}

// ---------------- exclusive scan of g_cnt -> g_rs (3 kernels) ----------------
__global__ void k_scan1(int N) {
    __shared__ int sh[256];
    int i = blockIdx.x * 256 + threadIdx.x;
    int v = (i < N) ? g_cnt[i] : 0;
    sh[threadIdx.x] = v;
    __syncthreads();
    #pragma unroll
    for (int off = 1; off < 256; off <<= 1) {
        int t = (threadIdx.x >= off) ? sh[threadIdx.x - off] : 0;
        __syncthreads();
        sh[threadIdx.x] += t;
        __syncthreads();
    }
    if (i < N) g_excl[i] = sh[threadIdx.x] - v;
    if (threadIdx.x == 255) g_bsum[blockIdx.x] = sh[255];
}

__global__ void k_scan2(int nb, int N, int E) {
    __shared__ int sh[256];
    int v = (threadIdx.x < nb) ? g_bsum[threadIdx.x] : 0;
    sh[threadIdx.x] = v;
    __syncthreads();
    #pragma unroll
    for (int off = 1; off < 256; off <<= 1) {
        int t = (threadIdx.x >= off) ? sh[threadIdx.x - off] : 0;
        __syncthreads();
        sh[threadIdx.x] += t;
        __syncthreads();
    }
    if (threadIdx.x < nb) g_boff[threadIdx.x] = sh[threadIdx.x] - v;
    if (threadIdx.x == 0) g_rs[N] = E;
}

__global__ void k_scan3(int N) {
    int i = blockIdx.x * blockDim.x + threadIdx.x;
    if (i < N) {
        int r = g_excl[i] + g_boff[i >> 8];
        g_rs[i]  = r;
        g_cur[i] = r;
    }
}

// ---------------- scatter edges into CSR (with precomputed norm) ----------------
__global__ void k_scatter(const int* __restrict__ ei, int E) {
    int e = blockIdx.x * blockDim.x + threadIdx.x;
    if (e >= E) return;
    int s = ei[e];
    int d = ei[E + e];
    int pos = atomicAdd(&g_cur[d], 1);
    g_csr[pos] = make_int2(s, __float_as_int(g_dinv[s] * g_dinv[d]));
}

// ---------------- GEMM1: H1 = X @ W1  (N x 512 @ 512 x 128) ----------------
__global__ __launch_bounds__(256) void k_gemm1(const float* __restrict__ X,
                                               const float* __restrict__ W,
                                               int N) {
    __shared__ float Xs[64][32];
    __shared__ float Ws[32][128];

    int tid = threadIdx.x;
    int ty  = tid >> 5;
    int tx  = tid & 31;
    int rowBase = blockIdx.x * 64;

    float acc[8][4];
    #pragma unroll
    for (int r = 0; r < 8; r++)
        #pragma unroll
        for (int c = 0; c < 4; c++) acc[r][c] = 0.0f;

    int lr = tid >> 3;
    int lc = (tid & 7) * 4;
    int wr = tid >> 5;
    int wc = (tid & 31) * 4;

    for (int kt = 0; kt < NFEAT; kt += 32) {
        #pragma unroll
        for (int h = 0; h < 2; h++) {
            int r = lr + 32 * h;
            int grow = rowBase + r;
            float4 v = make_float4(0.f, 0.f, 0.f, 0.f);
            if (grow < N)
                v = *(const float4*)(X + (size_t)grow * NFEAT + kt + lc);
            *(float4*)&Xs[r][lc] = v;
        }
        #pragma unroll
        for (int j = 0; j < 4; j++) {
            int r = wr + 8 * j;
            *(float4*)&Ws[r][wc] =
                *(const float4*)(W + (size_t)(kt + r) * HID + wc);
        }
        __syncthreads();

        #pragma unroll
        for (int k = 0; k < 32; k++) {
            float4 b = *(const float4*)&Ws[k][tx * 4];
            #pragma unroll
            for (int r = 0; r < 8; r++) {
                float a = Xs[ty * 8 + r][k];
                acc[r][0] += a * b.x;
                acc[r][1] += a * b.y;
                acc[r][2] += a * b.z;
                acc[r][3] += a * b.w;
            }
        }
        __syncthreads();
    }

    #pragma unroll
    for (int r = 0; r < 8; r++) {
        int grow = rowBase + ty * 8 + r;
        if (grow < N)
            *(float4*)(g_H1 + (size_t)grow * HID + tx * 4) =
                make_float4(acc[r][0], acc[r][1], acc[r][2], acc[r][3]);
    }
}

// ---------------- layer-1 aggregation: warp per node, no atomics ----------------
// agg1[i] = relu( b1 + dinv[i]^2*H1[i] + sum_e nrm*H1[src] )
__global__ __launch_bounds__(256) void k_agg1(const float* __restrict__ b1, int N) {
    int w    = (blockIdx.x * blockDim.x + threadIdx.x) >> 5;
    int lane = threadIdx.x & 31;
    if (w >= N) return;

    float di = g_dinv[w];
    float s2 = di * di;
    float4 acc = ((const float4*)b1)[lane];
    float4 h   = *((const float4*)(g_H1 + (size_t)w * HID) + lane);
    acc.x += s2 * h.x; acc.y += s2 * h.y; acc.z += s2 * h.z; acc.w += s2 * h.w;

    int beg = g_rs[w];
    int end = g_rs[w + 1];
    for (int e = beg; e < end; e++) {
        int2 pr = g_csr[e];
        float nrm = __int_as_float(pr.y);
        float4 v = __ldg((const float4*)(g_H1 + (size_t)pr.x * HID) + lane);
        acc.x += nrm * v.x; acc.y += nrm * v.y;
        acc.z += nrm * v.z; acc.w += nrm * v.w;
    }

    acc.x = fmaxf(acc.x, 0.f); acc.y = fmaxf(acc.y, 0.f);
    acc.z = fmaxf(acc.z, 0.f); acc.w = fmaxf(acc.w, 0.f);
    *((float4*)(g_agg1 + (size_t)w * HID) + lane) = acc;
}

// ---------------- GEMM2: H2 = agg1 @ W2  (N x 128 @ 128 x 64) ----------------
__global__ __launch_bounds__(256) void k_gemm2(const float* __restrict__ W, int N) {
    __shared__ float Xs[64][32];
    __shared__ float Ws[32][64];

    int tid = threadIdx.x;
    int ty  = tid >> 4;
    int tx  = tid & 15;
    int rowBase = blockIdx.x * 64;

    float acc[4][4];
    #pragma unroll
    for (int r = 0; r < 4; r++)
        #pragma unroll
        for (int c = 0; c < 4; c++) acc[r][c] = 0.0f;

    int lr = tid >> 3;
    int lc = (tid & 7) * 4;
    int wr = tid >> 4;
    int wc = (tid & 15) * 4;

    for (int kt = 0; kt < HID; kt += 32) {
        #pragma unroll
        for (int h = 0; h < 2; h++) {
            int r = lr + 32 * h;
            int grow = rowBase + r;
            float4 v = make_float4(0.f, 0.f, 0.f, 0.f);
            if (grow < N)
                v = *(const float4*)(g_agg1 + (size_t)grow * HID + kt + lc);
            *(float4*)&Xs[r][lc] = v;
        }
        #pragma unroll
        for (int j = 0; j < 2; j++) {
            int r = wr + 16 * j;
            *(float4*)&Ws[r][wc] =
                *(const float4*)(W + (size_t)(kt + r) * NCLS + wc);
        }
        __syncthreads();

        #pragma unroll
        for (int k = 0; k < 32; k++) {
            float4 b = *(const float4*)&Ws[k][tx * 4];
            #pragma unroll
            for (int r = 0; r < 4; r++) {
                float a = Xs[ty * 4 + r][k];
                acc[r][0] += a * b.x;
                acc[r][1] += a * b.y;
                acc[r][2] += a * b.z;
                acc[r][3] += a * b.w;
            }
        }
        __syncthreads();
    }

    #pragma unroll
    for (int r = 0; r < 4; r++) {
        int grow = rowBase + ty * 4 + r;
        if (grow < N)
            *(float4*)(g_H2 + (size_t)grow * NCLS + tx * 4) =
                make_float4(acc[r][0], acc[r][1], acc[r][2], acc[r][3]);
    }
}

// ---------------- layer-2 aggregation: 16 lanes per node ----------------
// out[i] = b2 + dinv[i]^2*H2[i] + sum_e nrm*H2[src]
__global__ __launch_bounds__(256) void k_agg2(const float* __restrict__ b2,
                                              float* __restrict__ out, int N) {
    int t = blockIdx.x * blockDim.x + threadIdx.x;
    int i = t >> 4;
    int c = t & 15;
    if (i >= N) return;

    float di = g_dinv[i];
    float s2 = di * di;
    float4 acc = ((const float4*)b2)[c];
    float4 h   = *((const float4*)(g_H2 + (size_t)i * NCLS) + c);
    acc.x += s2 * h.x; acc.y += s2 * h.y; acc.z += s2 * h.z; acc.w += s2 * h.w;

    int beg = g_rs[i];
    int end = g_rs[i + 1];
    for (int e = beg; e < end; e++) {
        int2 pr = g_csr[e];
        float nrm = __int_as_float(pr.y);
        float4 v = __ldg((const float4*)(g_H2 + (size_t)pr.x * NCLS) + c);
        acc.x += nrm * v.x; acc.y += nrm * v.y;
        acc.z += nrm * v.z; acc.w += nrm * v.w;
    }

    *((float4*)(out + (size_t)i * NCLS) + c) = acc;
}

extern "C" void kernel_launch(void* const* d_in, const int* in_sizes, int n_in,
                              void* d_out, int out_size) {
    const float* x  = (const float*)d_in[0];
    const int*   ei = (const int*)  d_in[1];
    const float* W1 = (const float*)d_in[2];
    const float* b1 = (const float*)d_in[3];
    const float* W2 = (const float*)d_in[4];
    const float* b2 = (const float*)d_in[5];
    float* out = (float*)d_out;

    int N = in_sizes[0] / NFEAT;   // 50000
    int E = in_sizes[1] / 2;       // 640000
    int nb = (N + 255) / 256;      // scan blocks (196)

    // CSR build
    k_cnt_init<<<(N + 255) / 256, 256>>>(N);
    k_cnt_acc <<<(E + 255) / 256, 256>>>(ei, E);
    k_dinv    <<<(N + 255) / 256, 256>>>(N);
    k_scan1   <<<nb, 256>>>(N);
    k_scan2   <<<1, 256>>>(nb, N, E);
    k_scan3   <<<nb, 256>>>(N);
    k_scatter <<<(E + 255) / 256, 256>>>(ei, E);

    // layer 1
    k_gemm1<<<(N + 63) / 64, 256>>>(x, W1, N);
    k_agg1 <<<(N * 32 + 255) / 256, 256>>>(b1, N);

    // layer 2
    k_gemm2<<<(N + 63) / 64, 256>>>(W2, N);
    k_agg2 <<<(N * 16 + 255) / 256, 256>>>(b2, out, N);
}

// round 4
// speedup vs baseline: 2.6159x; 1.4877x over previous
#include <cuda_runtime.h>
#include <cuda_bf16.h>
#include <cstdint>

#define NFEAT 512
#define HID   128
#define NCLS  64
#define NMAX  50048
#define EMAX  640000

// ---------------- device scratch (no allocation allowed) ----------------
__device__ float g_dinv[NMAX];
__device__ int   g_cnt [NMAX];
__device__ int   g_excl[NMAX];
__device__ int   g_bsum[256];
__device__ int   g_boff[256];
__device__ int   g_rs  [NMAX + 1];
__device__ int   g_cur [NMAX];
__device__ int2  g_csr [EMAX];
__device__ float g_H1  [(size_t)NMAX * HID];
__device__ float g_agg1[(size_t)NMAX * HID];
__device__ float g_H2  [(size_t)NMAX * NCLS];
// W1 split into hi/lo bf16, transposed to [n][k] (k contiguous)
__device__ __nv_bfloat16 g_Bh[HID * NFEAT];
__device__ __nv_bfloat16 g_Bl[HID * NFEAT];

// ==================== small helpers ====================
__device__ __forceinline__ uint32_t smem_u32(const void* p) {
    uint32_t a;
    asm("{ .reg .u64 t; cvta.to.shared.u64 t, %1; cvt.u32.u64 %0, t; }"
        : "=r"(a) : "l"(p));
    return a;
}

__device__ __forceinline__ void ldm_x4(uint32_t& r0, uint32_t& r1,
                                       uint32_t& r2, uint32_t& r3, uint32_t addr) {
    asm volatile("ldmatrix.sync.aligned.m8n8.x4.shared.b16 {%0,%1,%2,%3}, [%4];"
                 : "=r"(r0), "=r"(r1), "=r"(r2), "=r"(r3) : "r"(addr));
}

__device__ __forceinline__ void mma_bf16(float& d0, float& d1, float& d2, float& d3,
                                         uint32_t a0, uint32_t a1, uint32_t a2, uint32_t a3,
                                         uint32_t b0, uint32_t b1) {
    asm volatile(
        "mma.sync.aligned.m16n8k16.row.col.f32.bf16.bf16.f32 "
        "{%0,%1,%2,%3}, {%4,%5,%6,%7}, {%8,%9}, {%0,%1,%2,%3};"
        : "+f"(d0), "+f"(d1), "+f"(d2), "+f"(d3)
        : "r"(a0), "r"(a1), "r"(a2), "r"(a3), "r"(b0), "r"(b1));
}

// ==================== CSR build ====================
__global__ void k_cnt_init(int N) {
    int i = blockIdx.x * blockDim.x + threadIdx.x;
    if (i < N) g_cnt[i] = 0;
}
__global__ void k_cnt_acc(const int* __restrict__ ei, int E) {
    int e = blockIdx.x * blockDim.x + threadIdx.x;
    if (e < E) atomicAdd(&g_cnt[ei[E + e]], 1);
}
__global__ void k_dinv(int N) {
    int i = blockIdx.x * blockDim.x + threadIdx.x;
    if (i < N) g_dinv[i] = rsqrtf((float)(g_cnt[i] + 1));
}
__global__ void k_scan1(int N) {
    __shared__ int sh[256];
    int i = blockIdx.x * 256 + threadIdx.x;
    int v = (i < N) ? g_cnt[i] : 0;
    sh[threadIdx.x] = v;
    __syncthreads();
    #pragma unroll
    for (int off = 1; off < 256; off <<= 1) {
        int t = (threadIdx.x >= off) ? sh[threadIdx.x - off] : 0;
        __syncthreads();
        sh[threadIdx.x] += t;
        __syncthreads();
    }
    if (i < N) g_excl[i] = sh[threadIdx.x] - v;
    if (threadIdx.x == 255) g_bsum[blockIdx.x] = sh[255];
}
__global__ void k_scan2(int nb, int N, int E) {
    __shared__ int sh[256];
    int v = (threadIdx.x < nb) ? g_bsum[threadIdx.x] : 0;
    sh[threadIdx.x] = v;
    __syncthreads();
    #pragma unroll
    for (int off = 1; off < 256; off <<= 1) {
        int t = (threadIdx.x >= off) ? sh[threadIdx.x - off] : 0;
        __syncthreads();
        sh[threadIdx.x] += t;
        __syncthreads();
    }
    if (threadIdx.x < nb) g_boff[threadIdx.x] = sh[threadIdx.x] - v;
    if (threadIdx.x == 0) g_rs[N] = E;
}
__global__ void k_scan3(int N) {
    int i = blockIdx.x * blockDim.x + threadIdx.x;
    if (i < N) {
        int r = g_excl[i] + g_boff[i >> 8];
        g_rs[i]  = r;
        g_cur[i] = r;
    }
}
__global__ void k_scatter(const int* __restrict__ ei, int E) {
    int e = blockIdx.x * blockDim.x + threadIdx.x;
    if (e >= E) return;
    int s = ei[e];
    int d = ei[E + e];
    int pos = atomicAdd(&g_cur[d], 1);
    g_csr[pos] = make_int2(s, __float_as_int(g_dinv[s] * g_dinv[d]));
}

// ==================== W1 prep: split + transpose ====================
// W1 [512 k][128 n] row-major -> g_Bh/g_Bl [128 n][512 k]
__global__ void k_prepW(const float* __restrict__ W) {
    int t = blockIdx.x * blockDim.x + threadIdx.x;
    if (t >= NFEAT * HID) return;
    int k = t >> 7;
    int n = t & 127;
    float v = W[t];
    __nv_bfloat16 h = __float2bfloat16(v);
    __nv_bfloat16 l = __float2bfloat16(v - __bfloat162float(h));
    g_Bh[n * NFEAT + k] = h;
    g_Bl[n * NFEAT + k] = l;
}

// ==================== GEMM1 via mma.sync bf16 split ====================
// CTA: 128x128, 8 warps (4x2), warp tile 32x64, BK=32, double-buffered smem.
// smem buffer (bf16, padded rows of 40 elems = 80B):
//   Ah 128x40 (10240B), Al (10240B), Bh 128x40 (10240B), Bl (10240B) -> 40960B/buf
#define STRB   80               // row stride bytes
#define BUFSZ  40960
#define OFF_AL 10240
#define OFF_BH 20480
#define OFF_BL 30720
#define NCHUNK (NFEAT / 32)     // 16
#define GSMEM_BYTES (2 * BUFSZ)

extern __shared__ __align__(128) unsigned char s_dyn[];

__global__ void __launch_bounds__(256) k_gemm1_mma(const float* __restrict__ X, int N) {
    uint32_t sb = smem_u32(s_dyn);
    int tid  = threadIdx.x;
    int wid  = tid >> 5;
    int lane = tid & 31;
    int warp_m = (wid & 3) * 32;
    int warp_n = (wid >> 2) * 64;
    int rowBase = blockIdx.x * 128;

    float acc[2][8][4];
    #pragma unroll
    for (int mt = 0; mt < 2; mt++)
        #pragma unroll
        for (int nt = 0; nt < 8; nt++)
            #pragma unroll
            for (int j = 0; j < 4; j++) acc[mt][nt][j] = 0.0f;

    // stage registers
    float4 xs[4];
    uint4  bhs[2], bls[2];

    // per-thread load coordinates
    int xrow = tid >> 3;            // using idx = tid + 256*i -> row = idx>>3
    int xseg = tid & 7;
    int bn   = tid >> 2;            // idx>>2
    int bseg = tid & 3;

    // ---- load helpers (macros to keep regs in scope) ----
    #define LOAD_X(c)                                                          \
        {                                                                      \
            _Pragma("unroll")                                                  \
            for (int i = 0; i < 4; i++) {                                      \
                int row = xrow + 32 * i;                                       \
                int grow = rowBase + row;                                      \
                if (grow > N - 1) grow = N - 1;                                \
                xs[i] = *(const float4*)(X + (size_t)grow * NFEAT + (c) * 32 + xseg * 4); \
            }                                                                  \
        }
    #define LOAD_B(c)                                                          \
        {                                                                      \
            _Pragma("unroll")                                                  \
            for (int i = 0; i < 2; i++) {                                      \
                int n = bn + 64 * i;                                           \
                bhs[i] = *(const uint4*)(g_Bh + (size_t)n * NFEAT + (c) * 32 + bseg * 8); \
                bls[i] = *(const uint4*)(g_Bl + (size_t)n * NFEAT + (c) * 32 + bseg * 8); \
            }                                                                  \
        }
    #define STORE_CHUNK(b)                                                     \
        {                                                                      \
            unsigned char* base = s_dyn + (b) * BUFSZ;                         \
            _Pragma("unroll")                                                  \
            for (int i = 0; i < 4; i++) {                                      \
                int row = xrow + 32 * i;                                       \
                float f[4] = {xs[i].x, xs[i].y, xs[i].z, xs[i].w};             \
                uint32_t hi[2], lo[2];                                         \
                _Pragma("unroll")                                              \
                for (int j = 0; j < 2; j++) {                                  \
                    __nv_bfloat16 ha = __float2bfloat16(f[2*j]);               \
                    __nv_bfloat16 hb = __float2bfloat16(f[2*j+1]);             \
                    __nv_bfloat162 hp; hp.x = ha; hp.y = hb;                   \
                    __nv_bfloat162 lp = __floats2bfloat162_rn(                 \
                        f[2*j]   - __bfloat162float(ha),                       \
                        f[2*j+1] - __bfloat162float(hb));                      \
                    hi[j] = *(uint32_t*)&hp;                                   \
                    lo[j] = *(uint32_t*)&lp;                                   \
                }                                                              \
                uint32_t off = row * STRB + xseg * 8;                          \
                *(uint2*)(base + off)          = make_uint2(hi[0], hi[1]);     \
                *(uint2*)(base + OFF_AL + off) = make_uint2(lo[0], lo[1]);     \
            }                                                                  \
            _Pragma("unroll")                                                  \
            for (int i = 0; i < 2; i++) {                                      \
                int n = bn + 64 * i;                                           \
                uint32_t off = n * STRB + bseg * 16;                           \
                *(uint4*)(base + OFF_BH + off) = bhs[i];                       \
                *(uint4*)(base + OFF_BL + off) = bls[i];                       \
            }                                                                  \
        }

    LOAD_X(0); LOAD_B(0);
    STORE_CHUNK(0);
    __syncthreads();

    // precomputed lane address components (bytes within buffer)
    uint32_t aRowOff = (warp_m + (lane & 15)) * STRB + ((lane & 16) ? 16 : 0);
    uint32_t bRowSel = (lane & 7) + ((lane & 16) ? 8 : 0);
    uint32_t bKoff   = (lane & 8) ? 16 : 0;

    #pragma unroll 1
    for (int c = 0; c < NCHUNK; c++) {
        int cur = c & 1;
        if (c + 1 < NCHUNK) { LOAD_X(c + 1); LOAD_B(c + 1); }

        uint32_t base = sb + cur * BUFSZ;
        #pragma unroll
        for (int ka = 0; ka < 2; ka++) {
            uint32_t k0b = ka * 32;   // 16 bf16 = 32 bytes

            uint32_t ah[2][4], al[2][4];
            #pragma unroll
            for (int mt = 0; mt < 2; mt++) {
                uint32_t aaddr = base + aRowOff + mt * (16 * STRB) + k0b;
                ldm_x4(ah[mt][0], ah[mt][1], ah[mt][2], ah[mt][3], aaddr);
                ldm_x4(al[mt][0], al[mt][1], al[mt][2], al[mt][3], aaddr + OFF_AL);
            }

            uint32_t bh[8][2], bl[8][2];
            #pragma unroll
            for (int np = 0; np < 4; np++) {
                uint32_t brow = warp_n + np * 16 + bRowSel;
                uint32_t baddr = base + OFF_BH + brow * STRB + k0b + bKoff;
                ldm_x4(bh[2*np][0], bh[2*np][1], bh[2*np+1][0], bh[2*np+1][1], baddr);
                ldm_x4(bl[2*np][0], bl[2*np][1], bl[2*np+1][0], bl[2*np+1][1],
                       baddr + (OFF_BL - OFF_BH));
            }

            #pragma unroll
            for (int mt = 0; mt < 2; mt++)
                #pragma unroll
                for (int nt = 0; nt < 8; nt++) {
                    mma_bf16(acc[mt][nt][0], acc[mt][nt][1], acc[mt][nt][2], acc[mt][nt][3],
                             ah[mt][0], ah[mt][1], ah[mt][2], ah[mt][3],
                             bh[nt][0], bh[nt][1]);
                    mma_bf16(acc[mt][nt][0], acc[mt][nt][1], acc[mt][nt][2], acc[mt][nt][3],
                             ah[mt][0], ah[mt][1], ah[mt][2], ah[mt][3],
                             bl[nt][0], bl[nt][1]);
                    mma_bf16(acc[mt][nt][0], acc[mt][nt][1], acc[mt][nt][2], acc[mt][nt][3],
                             al[mt][0], al[mt][1], al[mt][2], al[mt][3],
                             bh[nt][0], bh[nt][1]);
                }
        }

        if (c + 1 < NCHUNK) { STORE_CHUNK(cur ^ 1); }
        __syncthreads();
    }

    // ---- epilogue ----
    int r0 = rowBase + warp_m + (lane >> 2);
    int cc = warp_n + 2 * (lane & 3);
    #pragma unroll
    for (int mt = 0; mt < 2; mt++) {
        int ra = r0 + mt * 16;
        int rb = ra + 8;
        #pragma unroll
        for (int nt = 0; nt < 8; nt++) {
            int col = cc + nt * 8;
            if (ra < N)
                *(float2*)(g_H1 + (size_t)ra * HID + col) =
                    make_float2(acc[mt][nt][0], acc[mt][nt][1]);
            if (rb < N)
                *(float2*)(g_H1 + (size_t)rb * HID + col) =
                    make_float2(acc[mt][nt][2], acc[mt][nt][3]);
        }
    }
    #undef LOAD_X
    #undef LOAD_B
    #undef STORE_CHUNK
}

// ==================== layer-1 aggregation (warp per node) ====================
__global__ __launch_bounds__(256) void k_agg1(const float* __restrict__ b1, int N) {
    int w    = (blockIdx.x * blockDim.x + threadIdx.x) >> 5;
    int lane = threadIdx.x & 31;
    if (w >= N) return;

    float di = g_dinv[w];
    float s2 = di * di;
    float4 acc = ((const float4*)b1)[lane];
    float4 h   = *((const float4*)(g_H1 + (size_t)w * HID) + lane);
    acc.x += s2 * h.x; acc.y += s2 * h.y; acc.z += s2 * h.z; acc.w += s2 * h.w;

    int beg = g_rs[w];
    int end = g_rs[w + 1];
    for (int e = beg; e < end; e++) {
        int2 pr = g_csr[e];
        float nrm = __int_as_float(pr.y);
        float4 v = __ldg((const float4*)(g_H1 + (size_t)pr.x * HID) + lane);
        acc.x += nrm * v.x; acc.y += nrm * v.y;
        acc.z += nrm * v.z; acc.w += nrm * v.w;
    }

    acc.x = fmaxf(acc.x, 0.f); acc.y = fmaxf(acc.y, 0.f);
    acc.z = fmaxf(acc.z, 0.f); acc.w = fmaxf(acc.w, 0.f);
    *((float4*)(g_agg1 + (size_t)w * HID) + lane) = acc;
}

// ==================== GEMM2 (SIMT): H2 = agg1 @ W2 ====================
__global__ __launch_bounds__(256) void k_gemm2(const float* __restrict__ W, int N) {
    __shared__ float Xs[64][32];
    __shared__ float Ws[32][64];

    int tid = threadIdx.x;
    int ty  = tid >> 4;
    int tx  = tid & 15;
    int rowBase = blockIdx.x * 64;

    float acc[4][4];
    #pragma unroll
    for (int r = 0; r < 4; r++)
        #pragma unroll
        for (int c = 0; c < 4; c++) acc[r][c] = 0.0f;

    int lr = tid >> 3;
    int lc = (tid & 7) * 4;
    int wr = tid >> 4;
    int wc = (tid & 15) * 4;

    for (int kt = 0; kt < HID; kt += 32) {
        #pragma unroll
        for (int h = 0; h < 2; h++) {
            int r = lr + 32 * h;
            int grow = rowBase + r;
            float4 v = make_float4(0.f, 0.f, 0.f, 0.f);
            if (grow < N)
                v = *(const float4*)(g_agg1 + (size_t)grow * HID + kt + lc);
            *(float4*)&Xs[r][lc] = v;
        }
        #pragma unroll
        for (int j = 0; j < 2; j++) {
            int r = wr + 16 * j;
            *(float4*)&Ws[r][wc] =
                *(const float4*)(W + (size_t)(kt + r) * NCLS + wc);
        }
        __syncthreads();

        #pragma unroll
        for (int k = 0; k < 32; k++) {
            float4 b = *(const float4*)&Ws[k][tx * 4];
            #pragma unroll
            for (int r = 0; r < 4; r++) {
                float a = Xs[ty * 4 + r][k];
                acc[r][0] += a * b.x;
                acc[r][1] += a * b.y;
                acc[r][2] += a * b.z;
                acc[r][3] += a * b.w;
            }
        }
        __syncthreads();
    }

    #pragma unroll
    for (int r = 0; r < 4; r++) {
        int grow = rowBase + ty * 4 + r;
        if (grow < N)
            *(float4*)(g_H2 + (size_t)grow * NCLS + tx * 4) =
                make_float4(acc[r][0], acc[r][1], acc[r][2], acc[r][3]);
    }
}

// ==================== layer-2 aggregation (16 lanes per node) ====================
__global__ __launch_bounds__(256) void k_agg2(const float* __restrict__ b2,
                                              float* __restrict__ out, int N) {
    int t = blockIdx.x * blockDim.x + threadIdx.x;
    int i = t >> 4;
    int c = t & 15;
    if (i >= N) return;

    float di = g_dinv[i];
    float s2 = di * di;
    float4 acc = ((const float4*)b2)[c];
    float4 h   = *((const float4*)(g_H2 + (size_t)i * NCLS) + c);
    acc.x += s2 * h.x; acc.y += s2 * h.y; acc.z += s2 * h.z; acc.w += s2 * h.w;

    int beg = g_rs[i];
    int end = g_rs[i + 1];
    for (int e = beg; e < end; e++) {
        int2 pr = g_csr[e];
        float nrm = __int_as_float(pr.y);
        float4 v = __ldg((const float4*)(g_H2 + (size_t)pr.x * NCLS) + c);
        acc.x += nrm * v.x; acc.y += nrm * v.y;
        acc.z += nrm * v.z; acc.w += nrm * v.w;
    }

    *((float4*)(out + (size_t)i * NCLS) + c) = acc;
}

extern "C" void kernel_launch(void* const* d_in, const int* in_sizes, int n_in,
                              void* d_out, int out_size) {
    const float* x  = (const float*)d_in[0];
    const int*   ei = (const int*)  d_in[1];
    const float* W1 = (const float*)d_in[2];
    const float* b1 = (const float*)d_in[3];
    const float* W2 = (const float*)d_in[4];
    const float* b2 = (const float*)d_in[5];
    float* out = (float*)d_out;

    int N = in_sizes[0] / NFEAT;   // 50000
    int E = in_sizes[1] / 2;       // 640000
    int nb = (N + 255) / 256;

    cudaFuncSetAttribute(k_gemm1_mma, cudaFuncAttributeMaxDynamicSharedMemorySize,
                         GSMEM_BYTES);

    // CSR build
    k_cnt_init<<<(N + 255) / 256, 256>>>(N);
    k_cnt_acc <<<(E + 255) / 256, 256>>>(ei, E);
    k_dinv    <<<(N + 255) / 256, 256>>>(N);
    k_scan1   <<<nb, 256>>>(N);
    k_scan2   <<<1, 256>>>(nb, N, E);
    k_scan3   <<<nb, 256>>>(N);
    k_scatter <<<(E + 255) / 256, 256>>>(ei, E);

    // W1 prep (split + transpose)
    k_prepW<<<(NFEAT * HID + 255) / 256, 256>>>(W1);

    // layer 1
    k_gemm1_mma<<<(N + 127) / 128, 256, GSMEM_BYTES>>>(x, N);
    k_agg1     <<<(N * 32 + 255) / 256, 256>>>(b1, N);

    // layer 2
    k_gemm2<<<(N + 63) / 64, 256>>>(W2, N);
    k_agg2 <<<(N * 16 + 255) / 256, 256>>>(b2, out, N);
}

// round 5
// speedup vs baseline: 3.1192x; 1.1924x over previous
#include <cuda_runtime.h>
#include <cuda_bf16.h>
#include <cstdint>

#define NFEAT 512
#define HID   128
#define NCLS  64
#define NMAX  50048
#define EMAX  640000

// ---------------- device scratch (no allocation allowed) ----------------
__device__ float g_dinv[NMAX];
__device__ int   g_cnt [NMAX];
__device__ int   g_excl[NMAX];
__device__ int   g_bsum[256];
__device__ int   g_boff[256];
__device__ int   g_rs  [NMAX + 1];
__device__ int   g_cur [NMAX];
__device__ int2  g_csr [EMAX];
__device__ float g_H1  [(size_t)NMAX * HID];
__device__ float g_agg1[(size_t)NMAX * HID];
__device__ float g_H2  [(size_t)NMAX * NCLS];
// W1 split hi/lo bf16, transposed to [n][k]
__device__ __nv_bfloat16 g_Bh[HID * NFEAT];
__device__ __nv_bfloat16 g_Bl[HID * NFEAT];
// W2 split hi/lo bf16, transposed to [n][k]
__device__ __nv_bfloat16 g_B2h[NCLS * HID];
__device__ __nv_bfloat16 g_B2l[NCLS * HID];

// ==================== helpers ====================
__device__ __forceinline__ uint32_t smem_u32(const void* p) {
    uint32_t a;
    asm("{ .reg .u64 t; cvta.to.shared.u64 t, %1; cvt.u32.u64 %0, t; }"
        : "=r"(a) : "l"(p));
    return a;
}

__device__ __forceinline__ void ldm_x4(uint32_t& r0, uint32_t& r1,
                                       uint32_t& r2, uint32_t& r3, uint32_t addr) {
    asm volatile("ldmatrix.sync.aligned.m8n8.x4.shared.b16 {%0,%1,%2,%3}, [%4];"
                 : "=r"(r0), "=r"(r1), "=r"(r2), "=r"(r3) : "r"(addr));
}

__device__ __forceinline__ void mma_bf16(float& d0, float& d1, float& d2, float& d3,
                                         uint32_t a0, uint32_t a1, uint32_t a2, uint32_t a3,
                                         uint32_t b0, uint32_t b1) {
    asm volatile(
        "mma.sync.aligned.m16n8k16.row.col.f32.bf16.bf16.f32 "
        "{%0,%1,%2,%3}, {%4,%5,%6,%7}, {%8,%9}, {%0,%1,%2,%3};"
        : "+f"(d0), "+f"(d1), "+f"(d2), "+f"(d3)
        : "r"(a0), "r"(a1), "r"(a2), "r"(a3), "r"(b0), "r"(b1));
}

__device__ __forceinline__ void cp16(uint32_t dst, const void* src) {
    asm volatile("cp.async.cg.shared.global [%0], [%1], 16;" :: "r"(dst), "l"(src));
}
#define CP_COMMIT() asm volatile("cp.async.commit_group;" ::: "memory")
#define CP_WAIT0()  asm volatile("cp.async.wait_group 0;" ::: "memory")

// ==================== CSR build ====================
__global__ void k_cnt_init(int N) {
    int i = blockIdx.x * blockDim.x + threadIdx.x;
    if (i < N) g_cnt[i] = 0;
}
__global__ void k_cnt_acc(const int* __restrict__ ei, int E) {
    int e = blockIdx.x * blockDim.x + threadIdx.x;
    if (e < E) atomicAdd(&g_cnt[ei[E + e]], 1);
}
// scan1 also produces dinv (fused)
__global__ void k_scan1(int N) {
    __shared__ int sh[256];
    int i = blockIdx.x * 256 + threadIdx.x;
    int v = (i < N) ? g_cnt[i] : 0;
    if (i < N) g_dinv[i] = rsqrtf((float)(v + 1));
    sh[threadIdx.x] = v;
    __syncthreads();
    #pragma unroll
    for (int off = 1; off < 256; off <<= 1) {
        int t = (threadIdx.x >= off) ? sh[threadIdx.x - off] : 0;
        __syncthreads();
        sh[threadIdx.x] += t;
        __syncthreads();
    }
    if (i < N) g_excl[i] = sh[threadIdx.x] - v;
    if (threadIdx.x == 255) g_bsum[blockIdx.x] = sh[255];
}
__global__ void k_scan2(int nb, int N, int E) {
    __shared__ int sh[256];
    int v = (threadIdx.x < nb) ? g_bsum[threadIdx.x] : 0;
    sh[threadIdx.x] = v;
    __syncthreads();
    #pragma unroll
    for (int off = 1; off < 256; off <<= 1) {
        int t = (threadIdx.x >= off) ? sh[threadIdx.x - off] : 0;
        __syncthreads();
        sh[threadIdx.x] += t;
        __syncthreads();
    }
    if (threadIdx.x < nb) g_boff[threadIdx.x] = sh[threadIdx.x] - v;
    if (threadIdx.x == 0) g_rs[N] = E;
}
__global__ void k_scan3(int N) {
    int i = blockIdx.x * blockDim.x + threadIdx.x;
    if (i < N) {
        int r = g_excl[i] + g_boff[i >> 8];
        g_rs[i]  = r;
        g_cur[i] = r;
    }
}
__global__ void k_scatter(const int* __restrict__ ei, int E) {
    int e = blockIdx.x * blockDim.x + threadIdx.x;
    if (e >= E) return;
    int s = ei[e];
    int d = ei[E + e];
    int pos = atomicAdd(&g_cur[d], 1);
    g_csr[pos] = make_int2(s, __float_as_int(g_dinv[s] * g_dinv[d]));
}

// ==================== weight prep ====================
__global__ void k_prepW(const float* __restrict__ W) {
    int t = blockIdx.x * blockDim.x + threadIdx.x;
    if (t >= NFEAT * HID) return;
    int k = t >> 7;
    int n = t & 127;
    float v = W[t];
    __nv_bfloat16 h = __float2bfloat16(v);
    __nv_bfloat16 l = __float2bfloat16(v - __bfloat162float(h));
    g_Bh[n * NFEAT + k] = h;
    g_Bl[n * NFEAT + k] = l;
}
__global__ void k_prepW2(const float* __restrict__ W) {
    int t = blockIdx.x * blockDim.x + threadIdx.x;
    if (t >= HID * NCLS) return;
    int k = t >> 6;
    int n = t & 63;
    float v = W[t];
    __nv_bfloat16 h = __float2bfloat16(v);
    __nv_bfloat16 l = __float2bfloat16(v - __bfloat162float(h));
    g_B2h[n * HID + k] = h;
    g_B2l[n * HID + k] = l;
}

// ==================== GEMM1 via mma.sync bf16 split ====================
#define STRB   80
#define BUFSZ  40960
#define OFF_AL 10240
#define OFF_BH 20480
#define OFF_BL 30720
#define NCHUNK (NFEAT / 32)     // 16
#define GSMEM_BYTES (2 * BUFSZ)

extern __shared__ __align__(128) unsigned char s_dyn[];

__global__ void __launch_bounds__(256) k_gemm1_mma(const float* __restrict__ X, int N) {
    uint32_t sb = smem_u32(s_dyn);
    int tid  = threadIdx.x;
    int wid  = tid >> 5;
    int lane = tid & 31;
    int warp_m = (wid & 3) * 32;
    int warp_n = (wid >> 2) * 64;
    int rowBase = blockIdx.x * 128;

    float acc[2][8][4];
    #pragma unroll
    for (int mt = 0; mt < 2; mt++)
        #pragma unroll
        for (int nt = 0; nt < 8; nt++)
            #pragma unroll
            for (int j = 0; j < 4; j++) acc[mt][nt][j] = 0.0f;

    float4 xs[4];
    int xrow = tid >> 3;
    int xseg = tid & 7;
    int bn   = tid >> 2;
    int bseg = tid & 3;

    #define LOAD_X(c)                                                          \
        {                                                                      \
            _Pragma("unroll")                                                  \
            for (int i = 0; i < 4; i++) {                                      \
                int row = xrow + 32 * i;                                       \
                int grow = rowBase + row;                                      \
                if (grow > N - 1) grow = N - 1;                                \
                xs[i] = *(const float4*)(X + (size_t)grow * NFEAT + (c) * 32 + xseg * 4); \
            }                                                                  \
        }
    #define CP_B(c, b)                                                         \
        {                                                                      \
            _Pragma("unroll")                                                  \
            for (int i = 0; i < 2; i++) {                                      \
                int n = bn + 64 * i;                                           \
                uint32_t dst = sb + (b) * BUFSZ + OFF_BH + n * STRB + bseg * 16; \
                cp16(dst, g_Bh + (size_t)n * NFEAT + (c) * 32 + bseg * 8);      \
                cp16(dst + (OFF_BL - OFF_BH),                                   \
                     g_Bl + (size_t)n * NFEAT + (c) * 32 + bseg * 8);           \
            }                                                                  \
        }
    #define STORE_A(b)                                                         \
        {                                                                      \
            unsigned char* base = s_dyn + (b) * BUFSZ;                         \
            _Pragma("unroll")                                                  \
            for (int i = 0; i < 4; i++) {                                      \
                int row = xrow + 32 * i;                                       \
                float f[4] = {xs[i].x, xs[i].y, xs[i].z, xs[i].w};             \
                uint32_t hi[2], lo[2];                                         \
                _Pragma("unroll")                                              \
                for (int j = 0; j < 2; j++) {                                  \
                    __nv_bfloat16 ha = __float2bfloat16(f[2*j]);               \
                    __nv_bfloat16 hb = __float2bfloat16(f[2*j+1]);             \
                    __nv_bfloat162 hp; hp.x = ha; hp.y = hb;                   \
                    __nv_bfloat162 lp = __floats2bfloat162_rn(                 \
                        f[2*j]   - __bfloat162float(ha),                       \
                        f[2*j+1] - __bfloat162float(hb));                      \
                    hi[j] = *(uint32_t*)&hp;                                   \
                    lo[j] = *(uint32_t*)&lp;                                   \
                }                                                              \
                uint32_t off = row * STRB + xseg * 8;                          \
                *(uint2*)(base + off)          = make_uint2(hi[0], hi[1]);     \
                *(uint2*)(base + OFF_AL + off) = make_uint2(lo[0], lo[1]);     \
            }                                                                  \
        }

    CP_B(0, 0); CP_COMMIT();
    LOAD_X(0);
    STORE_A(0);
    CP_WAIT0();
    __syncthreads();

    uint32_t aRowOff = (warp_m + (lane & 15)) * STRB + ((lane & 16) ? 16 : 0);
    uint32_t bRowSel = (lane & 7) + ((lane & 16) ? 8 : 0);
    uint32_t bKoff   = (lane & 8) ? 16 : 0;

    #pragma unroll 1
    for (int c = 0; c < NCHUNK; c++) {
        int cur = c & 1;
        if (c + 1 < NCHUNK) {
            CP_B(c + 1, cur ^ 1); CP_COMMIT();
            LOAD_X(c + 1);
        }

        uint32_t base = sb + cur * BUFSZ;
        #pragma unroll
        for (int ka = 0; ka < 2; ka++) {
            uint32_t k0b = ka * 32;

            uint32_t ah[2][4], al[2][4];
            #pragma unroll
            for (int mt = 0; mt < 2; mt++) {
                uint32_t aaddr = base + aRowOff + mt * (16 * STRB) + k0b;
                ldm_x4(ah[mt][0], ah[mt][1], ah[mt][2], ah[mt][3], aaddr);
                ldm_x4(al[mt][0], al[mt][1], al[mt][2], al[mt][3], aaddr + OFF_AL);
            }

            uint32_t bh[8][2], bl[8][2];
            #pragma unroll
            for (int np = 0; np < 4; np++) {
                uint32_t brow = warp_n + np * 16 + bRowSel;
                uint32_t baddr = base + OFF_BH + brow * STRB + k0b + bKoff;
                ldm_x4(bh[2*np][0], bh[2*np][1], bh[2*np+1][0], bh[2*np+1][1], baddr);
                ldm_x4(bl[2*np][0], bl[2*np][1], bl[2*np+1][0], bl[2*np+1][1],
                       baddr + (OFF_BL - OFF_BH));
            }

            #pragma unroll
            for (int mt = 0; mt < 2; mt++)
                #pragma unroll
                for (int nt = 0; nt < 8; nt++) {
                    mma_bf16(acc[mt][nt][0], acc[mt][nt][1], acc[mt][nt][2], acc[mt][nt][3],
                             ah[mt][0], ah[mt][1], ah[mt][2], ah[mt][3],
                             bh[nt][0], bh[nt][1]);
                    mma_bf16(acc[mt][nt][0], acc[mt][nt][1], acc[mt][nt][2], acc[mt][nt][3],
                             ah[mt][0], ah[mt][1], ah[mt][2], ah[mt][3],
                             bl[nt][0], bl[nt][1]);
                    mma_bf16(acc[mt][nt][0], acc[mt][nt][1], acc[mt][nt][2], acc[mt][nt][3],
                             al[mt][0], al[mt][1], al[mt][2], al[mt][3],
                             bh[nt][0], bh[nt][1]);
                }
        }

        if (c + 1 < NCHUNK) {
            STORE_A(cur ^ 1);
            CP_WAIT0();
        }
        __syncthreads();
    }

    int r0 = rowBase + warp_m + (lane >> 2);
    int cc = warp_n + 2 * (lane & 3);
    #pragma unroll
    for (int mt = 0; mt < 2; mt++) {
        int ra = r0 + mt * 16;
        int rb = ra + 8;
        #pragma unroll
        for (int nt = 0; nt < 8; nt++) {
            int col = cc + nt * 8;
            if (ra < N)
                *(float2*)(g_H1 + (size_t)ra * HID + col) =
                    make_float2(acc[mt][nt][0], acc[mt][nt][1]);
            if (rb < N)
                *(float2*)(g_H1 + (size_t)rb * HID + col) =
                    make_float2(acc[mt][nt][2], acc[mt][nt][3]);
        }
    }
    #undef LOAD_X
    #undef CP_B
    #undef STORE_A
}

// ==================== layer-1 aggregation (warp per node) ====================
__global__ __launch_bounds__(256) void k_agg1(const float* __restrict__ b1, int N) {
    int w    = (blockIdx.x * blockDim.x + threadIdx.x) >> 5;
    int lane = threadIdx.x & 31;
    if (w >= N) return;

    float di = g_dinv[w];
    float s2 = di * di;
    float4 acc = ((const float4*)b1)[lane];
    float4 h   = *((const float4*)(g_H1 + (size_t)w * HID) + lane);
    acc.x += s2 * h.x; acc.y += s2 * h.y; acc.z += s2 * h.z; acc.w += s2 * h.w;

    int beg = g_rs[w];
    int end = g_rs[w + 1];
    for (int e = beg; e < end; e++) {
        int2 pr = g_csr[e];
        float nrm = __int_as_float(pr.y);
        float4 v = __ldg((const float4*)(g_H1 + (size_t)pr.x * HID) + lane);
        acc.x += nrm * v.x; acc.y += nrm * v.y;
        acc.z += nrm * v.z; acc.w += nrm * v.w;
    }

    acc.x = fmaxf(acc.x, 0.f); acc.y = fmaxf(acc.y, 0.f);
    acc.z = fmaxf(acc.z, 0.f); acc.w = fmaxf(acc.w, 0.f);
    *((float4*)(g_agg1 + (size_t)w * HID) + lane) = acc;
}

// ==================== GEMM2 via mma.sync bf16 split (128x64 tile) ====================
#define BUF2SZ  30720
#define OFF2_AL 10240
#define OFF2_BH 20480
#define OFF2_BL 25600
#define NCHUNK2 (HID / 32)      // 4
#define G2SMEM_BYTES (2 * BUF2SZ)

__global__ void __launch_bounds__(256) k_gemm2_mma(int N) {
    uint32_t sb = smem_u32(s_dyn);
    int tid  = threadIdx.x;
    int wid  = tid >> 5;
    int lane = tid & 31;
    int warp_m = (wid & 3) * 32;
    int warp_n = (wid >> 2) * 32;
    int rowBase = blockIdx.x * 128;

    float acc[2][4][4];
    #pragma unroll
    for (int mt = 0; mt < 2; mt++)
        #pragma unroll
        for (int nt = 0; nt < 4; nt++)
            #pragma unroll
            for (int j = 0; j < 4; j++) acc[mt][nt][j] = 0.0f;

    float4 xs[4];
    int xrow = tid >> 3;
    int xseg = tid & 7;
    int bn   = tid >> 2;   // 0..63
    int bseg = tid & 3;

    #define LOAD_X2(c)                                                         \
        {                                                                      \
            _Pragma("unroll")                                                  \
            for (int i = 0; i < 4; i++) {                                      \
                int row = xrow + 32 * i;                                       \
                int grow = rowBase + row;                                      \
                if (grow > N - 1) grow = N - 1;                                \
                xs[i] = *(const float4*)(g_agg1 + (size_t)grow * HID + (c) * 32 + xseg * 4); \
            }                                                                  \
        }
    #define CP_B2(c, b)                                                        \
        {                                                                      \
            uint32_t dst = sb + (b) * BUF2SZ + OFF2_BH + bn * STRB + bseg * 16; \
            cp16(dst, g_B2h + (size_t)bn * HID + (c) * 32 + bseg * 8);          \
            cp16(dst + (OFF2_BL - OFF2_BH),                                     \
                 g_B2l + (size_t)bn * HID + (c) * 32 + bseg * 8);               \
        }
    #define STORE_A2(b)                                                        \
        {                                                                      \
            unsigned char* base = s_dyn + (b) * BUF2SZ;                        \
            _Pragma("unroll")                                                  \
            for (int i = 0; i < 4; i++) {                                      \
                int row = xrow + 32 * i;                                       \
                float f[4] = {xs[i].x, xs[i].y, xs[i].z, xs[i].w};             \
                uint32_t hi[2], lo[2];                                         \
                _Pragma("unroll")                                              \
                for (int j = 0; j < 2; j++) {                                  \
                    __nv_bfloat16 ha = __float2bfloat16(f[2*j]);               \
                    __nv_bfloat16 hb = __float2bfloat16(f[2*j+1]);             \
                    __nv_bfloat162 hp; hp.x = ha; hp.y = hb;                   \
                    __nv_bfloat162 lp = __floats2bfloat162_rn(                 \
                        f[2*j]   - __bfloat162float(ha),                       \
                        f[2*j+1] - __bfloat162float(hb));                      \
                    hi[j] = *(uint32_t*)&hp;                                   \
                    lo[j] = *(uint32_t*)&lp;                                   \
                }                                                              \
                uint32_t off = row * STRB + xseg * 8;                          \
                *(uint2*)(base + off)           = make_uint2(hi[0], hi[1]);    \
                *(uint2*)(base + OFF2_AL + off) = make_uint2(lo[0], lo[1]);    \
            }                                                                  \
        }

    CP_B2(0, 0); CP_COMMIT();
    LOAD_X2(0);
    STORE_A2(0);
    CP_WAIT0();
    __syncthreads();

    uint32_t aRowOff = (warp_m + (lane & 15)) * STRB + ((lane & 16) ? 16 : 0);
    uint32_t bRowSel = (lane & 7) + ((lane & 16) ? 8 : 0);
    uint32_t bKoff   = (lane & 8) ? 16 : 0;

    #pragma unroll 1
    for (int c = 0; c < NCHUNK2; c++) {
        int cur = c & 1;
        if (c + 1 < NCHUNK2) {
            CP_B2(c + 1, cur ^ 1); CP_COMMIT();
            LOAD_X2(c + 1);
        }

        uint32_t base = sb + cur * BUF2SZ;
        #pragma unroll
        for (int ka = 0; ka < 2; ka++) {
            uint32_t k0b = ka * 32;

            uint32_t ah[2][4], al[2][4];
            #pragma unroll
            for (int mt = 0; mt < 2; mt++) {
                uint32_t aaddr = base + aRowOff + mt * (16 * STRB) + k0b;
                ldm_x4(ah[mt][0], ah[mt][1], ah[mt][2], ah[mt][3], aaddr);
                ldm_x4(al[mt][0], al[mt][1], al[mt][2], al[mt][3], aaddr + OFF2_AL);
            }

            uint32_t bh[4][2], bl[4][2];
            #pragma unroll
            for (int np = 0; np < 2; np++) {
                uint32_t brow = warp_n + np * 16 + bRowSel;
                uint32_t baddr = base + OFF2_BH + brow * STRB + k0b + bKoff;
                ldm_x4(bh[2*np][0], bh[2*np][1], bh[2*np+1][0], bh[2*np+1][1], baddr);
                ldm_x4(bl[2*np][0], bl[2*np][1], bl[2*np+1][0], bl[2*np+1][1],
                       baddr + (OFF2_BL - OFF2_BH));
            }

            #pragma unroll
            for (int mt = 0; mt < 2; mt++)
                #pragma unroll
                for (int nt = 0; nt < 4; nt++) {
                    mma_bf16(acc[mt][nt][0], acc[mt][nt][1], acc[mt][nt][2], acc[mt][nt][3],
                             ah[mt][0], ah[mt][1], ah[mt][2], ah[mt][3],
                             bh[nt][0], bh[nt][1]);
                    mma_bf16(acc[mt][nt][0], acc[mt][nt][1], acc[mt][nt][2], acc[mt][nt][3],
                             ah[mt][0], ah[mt][1], ah[mt][2], ah[mt][3],
                             bl[nt][0], bl[nt][1]);
                    mma_bf16(acc[mt][nt][0], acc[mt][nt][1], acc[mt][nt][2], acc[mt][nt][3],
                             al[mt][0], al[mt][1], al[mt][2], al[mt][3],
                             bh[nt][0], bh[nt][1]);
                }
        }

        if (c + 1 < NCHUNK2) {
            STORE_A2(cur ^ 1);
            CP_WAIT0();
        }
        __syncthreads();
    }

    int r0 = rowBase + warp_m + (lane >> 2);
    int cc = warp_n + 2 * (lane & 3);
    #pragma unroll
    for (int mt = 0; mt < 2; mt++) {
        int ra = r0 + mt * 16;
        int rb = ra + 8;
        #pragma unroll
        for (int nt = 0; nt < 4; nt++) {
            int col = cc + nt * 8;
            if (ra < N)
                *(float2*)(g_H2 + (size_t)ra * NCLS + col) =
                    make_float2(acc[mt][nt][0], acc[mt][nt][1]);
            if (rb < N)
                *(float2*)(g_H2 + (size_t)rb * NCLS + col) =
                    make_float2(acc[mt][nt][2], acc[mt][nt][3]);
        }
    }
    #undef LOAD_X2
    #undef CP_B2
    #undef STORE_A2
}

// ==================== layer-2 aggregation (16 lanes per node) ====================
__global__ __launch_bounds__(256) void k_agg2(const float* __restrict__ b2,
                                              float* __restrict__ out, int N) {
    int t = blockIdx.x * blockDim.x + threadIdx.x;
    int i = t >> 4;
    int c = t & 15;
    if (i >= N) return;

    float di = g_dinv[i];
    float s2 = di * di;
    float4 acc = ((const float4*)b2)[c];
    float4 h   = *((const float4*)(g_H2 + (size_t)i * NCLS) + c);
    acc.x += s2 * h.x; acc.y += s2 * h.y; acc.z += s2 * h.z; acc.w += s2 * h.w;

    int beg = g_rs[i];
    int end = g_rs[i + 1];
    for (int e = beg; e < end; e++) {
        int2 pr = g_csr[e];
        float nrm = __int_as_float(pr.y);
        float4 v = __ldg((const float4*)(g_H2 + (size_t)pr.x * NCLS) + c);
        acc.x += nrm * v.x; acc.y += nrm * v.y;
        acc.z += nrm * v.z; acc.w += nrm * v.w;
    }

    *((float4*)(out + (size_t)i * NCLS) + c) = acc;
}

// ==================== launch ====================
struct AuxObjs {
    cudaStream_t s1;
    cudaEvent_t  e0, e1;
    AuxObjs() {
        cudaStreamCreateWithFlags(&s1, cudaStreamNonBlocking);
        cudaEventCreateWithFlags(&e0, cudaEventDisableTiming);
        cudaEventCreateWithFlags(&e1, cudaEventDisableTiming);
    }
};

extern "C" void kernel_launch(void* const* d_in, const int* in_sizes, int n_in,
                              void* d_out, int out_size) {
    static AuxObjs aux;   // created on first (non-captured) correctness call

    const float* x  = (const float*)d_in[0];
    const int*   ei = (const int*)  d_in[1];
    const float* W1 = (const float*)d_in[2];
    const float* b1 = (const float*)d_in[3];
    const float* W2 = (const float*)d_in[4];
    const float* b2 = (const float*)d_in[5];
    float* out = (float*)d_out;

    int N = in_sizes[0] / NFEAT;   // 50000
    int E = in_sizes[1] / 2;       // 640000
    int nb = (N + 255) / 256;

    cudaFuncSetAttribute(k_gemm1_mma, cudaFuncAttributeMaxDynamicSharedMemorySize,
                         GSMEM_BYTES);
    cudaFuncSetAttribute(k_gemm2_mma, cudaFuncAttributeMaxDynamicSharedMemorySize,
                         G2SMEM_BYTES);

    // Fork: CSR chain on aux.s1, GEMM path on main stream.
    cudaEventRecord(aux.e0, 0);
    cudaStreamWaitEvent(aux.s1, aux.e0, 0);

    // --- CSR branch (s1) ---
    k_cnt_init<<<(N + 255) / 256, 256, 0, aux.s1>>>(N);
    k_cnt_acc <<<(E + 255) / 256, 256, 0, aux.s1>>>(ei, E);
    k_scan1   <<<nb, 256, 0, aux.s1>>>(N);
    k_scan2   <<<1, 256, 0, aux.s1>>>(nb, N, E);
    k_scan3   <<<nb, 256, 0, aux.s1>>>(N);
    k_scatter <<<(E + 255) / 256, 256, 0, aux.s1>>>(ei, E);
    cudaEventRecord(aux.e1, aux.s1);

    // --- GEMM branch (main stream) ---
    k_prepW <<<(NFEAT * HID + 255) / 256, 256>>>(W1);
    k_prepW2<<<(HID * NCLS + 255) / 256, 256>>>(W2);
    k_gemm1_mma<<<(N + 127) / 128, 256, GSMEM_BYTES>>>(x, N);

    // Join
    cudaStreamWaitEvent(0, aux.e1, 0);

    k_agg1     <<<(N * 32 + 255) / 256, 256>>>(b1, N);
    k_gemm2_mma<<<(N + 127) / 128, 256, G2SMEM_BYTES>>>(N);
    k_agg2     <<<(N * 16 + 255) / 256, 256>>>(b2, out, N);
}